// round 15
// baseline (speedup 1.0000x reference)
#include <cuda_runtime.h>
#include <cstdint>
#include <cstddef>

// Problem dims
#define B_  512
#define S_  1024
#define I_  64
#define H_  128
#define G_  384   // 3*H
#define C_  10

// Scratch (device globals: allocation APIs are forbidden)
// g_xg layout: INTERLEAVED [b/4][s][g][4] so one rec-CTA's 4 batch rows for a
// given (s, gate) are 16 contiguous bytes -> single cp.async.16B per step.
__device__ float g_xg[(size_t)B_ * S_ * G_];
__device__ float g_h1[(size_t)B_ * S_ * H_];    // layer0 hidden outputs [b][s][h]

typedef unsigned long long u64;

__device__ __forceinline__ u64 pk2(float lo, float hi) {
    u64 r; asm("mov.b64 %0, {%1, %2};" : "=l"(r) : "f"(lo), "f"(hi)); return r;
}
__device__ __forceinline__ void upk2(u64 v, float& lo, float& hi) {
    asm("mov.b64 {%0, %1}, %2;" : "=f"(lo), "=f"(hi) : "l"(v));
}
__device__ __forceinline__ void fma2(u64& d, u64 a, u64 b) {
    asm("fma.rn.f32x2 %0, %1, %2, %0;" : "+l"(d) : "l"(a), "l"(b));
}

// MUFU.TANH — single-op tanh (sm_75+)
__device__ __forceinline__ float tanh_ap(float x) {
    float y; asm("tanh.approx.f32 %0, %1;" : "=f"(y) : "f"(x)); return y;
}
__device__ __forceinline__ float sig_ap(float x) {
    return fmaf(tanh_ap(0.5f * x), 0.5f, 0.5f);
}

__device__ __forceinline__ uint32_t smem_u32(const void* p) {
    uint32_t a;
    asm("{ .reg .u64 t; cvta.to.shared.u64 t, %1; cvt.u32.u64 %0, t; }"
        : "=r"(a) : "l"(p));
    return a;
}
// Predicated 16-byte cp.async (.cg: bypass L1, xg is read exactly once)
__device__ __forceinline__ void cp_async16(uint32_t dst, const float* src, int pred) {
    asm volatile(
        "{\n\t.reg .pred p;\n\tsetp.ne.u32 p, %2, 0;\n\t"
        "@p cp.async.cg.shared.global [%0], [%1], 16;\n\t}"
        :: "r"(dst), "l"(src), "r"(pred) : "memory");
}
__device__ __forceinline__ void cp_commit() {
    asm volatile("cp.async.commit_group;" ::: "memory");
}
__device__ __forceinline__ void cp_wait1() {
    asm volatile("cp.async.wait_group 1;" ::: "memory");
}

// ============================================================================
// Phase 1/3: xg = A @ W^T + bias, interleaved output (R9 version, 256 thr)
// ============================================================================
template<int K, bool A_IS_H1>
__global__ __launch_bounds__(256) void gemm_xg_kernel(
    const float* __restrict__ Ain, const float* __restrict__ W,
    const float* __restrict__ bias, int ntiles)
{
    extern __shared__ float smem[];
    float* Ws = smem;              // [K][384], k-major
    float* As = smem + K * G_;     // [64][K]
    const float* A = A_IS_H1 ? g_h1 : Ain;

    const int tid = threadIdx.x;
    constexpr int KQ = K / 4;
    constexpr int PF = (64 * KQ) / 256;

    for (int idx = tid; idx < G_ * KQ; idx += 256) {
        int kq = idx / G_;
        int g  = idx - kq * G_;
        float4 w4 = *reinterpret_cast<const float4*>(W + (size_t)g * K + 4 * kq);
        Ws[(4 * kq + 0) * G_ + g] = w4.x;
        Ws[(4 * kq + 1) * G_ + g] = w4.y;
        Ws[(4 * kq + 2) * G_ + g] = w4.z;
        Ws[(4 * kq + 3) * G_ + g] = w4.w;
    }

    const int cg = tid & 31;
    const int rg = tid >> 5;

    float4 bv[3];
#pragma unroll
    for (int gg = 0; gg < 3; ++gg)
        bv[gg] = *reinterpret_cast<const float4*>(bias + gg * H_ + 4 * cg);

    auto tile_src = [&](int tl, int i) -> const float4* {
        int idx = tid + 256 * i;
        int r   = idx / KQ;
        int c   = idx - r * KQ;
        int bq  = tl >> 6;
        int s0  = (tl & 63) << 4;
        size_t row = (size_t)(4 * bq + (r >> 4)) * S_ + s0 + (r & 15);
        return reinterpret_cast<const float4*>(A + row * K) + c;
    };

    int tile = blockIdx.x;
    float4 pf[PF];
    if (tile < ntiles) {
#pragma unroll
        for (int i = 0; i < PF; ++i) pf[i] = *tile_src(tile, i);
    }
    __syncthreads();

    for (; tile < ntiles; tile += gridDim.x) {
#pragma unroll
        for (int i = 0; i < PF; ++i)
            reinterpret_cast<float4*>(As)[tid + 256 * i] = pf[i];
        __syncthreads();

        int ntile = tile + gridDim.x;
        if (ntile < ntiles) {
#pragma unroll
            for (int i = 0; i < PF; ++i) pf[i] = *tile_src(ntile, i);
        }

        u64 acc[8][3][2];
#pragma unroll
        for (int r = 0; r < 8; ++r)
#pragma unroll
            for (int gg = 0; gg < 3; ++gg) {
                acc[r][gg][0] = 0ull;
                acc[r][gg][1] = 0ull;
            }

#pragma unroll 2
        for (int k4 = 0; k4 < K; k4 += 4) {
            float4 af[8];
#pragma unroll
            for (int r = 0; r < 8; ++r)
                af[r] = *reinterpret_cast<const float4*>(&As[(rg + 8 * r) * K + k4]);
#pragma unroll
            for (int kk = 0; kk < 4; ++kk) {
                ulonglong2 wp[3];
#pragma unroll
                for (int gg = 0; gg < 3; ++gg)
                    wp[gg] = *reinterpret_cast<const ulonglong2*>(
                        &Ws[(size_t)(k4 + kk) * G_ + gg * H_ + 4 * cg]);
#pragma unroll
                for (int r = 0; r < 8; ++r) {
                    float a = (kk == 0) ? af[r].x : (kk == 1) ? af[r].y
                            : (kk == 2) ? af[r].z : af[r].w;
                    u64 ad = pk2(a, a);
#pragma unroll
                    for (int gg = 0; gg < 3; ++gg) {
                        fma2(acc[r][gg][0], ad, wp[gg].x);
                        fma2(acc[r][gg][1], ad, wp[gg].y);
                    }
                }
            }
        }

        // Interleaved store: row r = rg + 8r' -> b-lane = r'>>1, si = r'&1
        {
            const int bq = tile >> 6;
            const int s0 = (tile & 63) << 4;
#pragma unroll
            for (int si = 0; si < 2; ++si) {
                const int s = s0 + rg + 8 * si;
                float* Crow = g_xg + ((size_t)bq * S_ + s) * (G_ * 4);
#pragma unroll
                for (int gg = 0; gg < 3; ++gg) {
                    float q0[4], q1[4], q2[4], q3[4];
#pragma unroll
                    for (int b = 0; b < 4; ++b) {
                        upk2(acc[2 * b + si][gg][0], q0[b], q1[b]);
                        upk2(acc[2 * b + si][gg][1], q2[b], q3[b]);
                    }
                    float* p = Crow + (gg * H_ + 4 * cg) * 4;
                    *reinterpret_cast<float4*>(p)      = make_float4(
                        q0[0] + bv[gg].x, q0[1] + bv[gg].x, q0[2] + bv[gg].x, q0[3] + bv[gg].x);
                    *reinterpret_cast<float4*>(p + 4)  = make_float4(
                        q1[0] + bv[gg].y, q1[1] + bv[gg].y, q1[2] + bv[gg].y, q1[3] + bv[gg].y);
                    *reinterpret_cast<float4*>(p + 8)  = make_float4(
                        q2[0] + bv[gg].z, q2[1] + bv[gg].z, q2[2] + bv[gg].z, q2[3] + bv[gg].z);
                    *reinterpret_cast<float4*>(p + 12) = make_float4(
                        q3[0] + bv[gg].w, q3[1] + bv[gg].w, q3[2] + bv[gg].w, q3[3] + bv[gg].w);
                }
            }
        }
        __syncthreads();
    }
}

// ============================================================================
// Phase 2/4: recurrent scan. 128 CTAs x 4 batch rows, 384 threads.
// W_hh k-pairs 0..23 in k-major smem (wsm, conflict-free LDS.64), pairs 24..63
// in 80 registers. Freed registers fund an explicit 1-iteration double-buffered
// lookahead of the h-loads and w-loads -> LDS latency covered by compute.
// rec<false> (layer 2) fuses the FC head from h_s at the end.
// ============================================================================
template<bool WRITE_ALL>
__global__ __launch_bounds__(384, 1) void gru_rec_kernel(
    const float* __restrict__ Whh, const float* __restrict__ bhh,
    const float* __restrict__ fw, const float* __restrict__ fb,
    float* __restrict__ out)
{
    // dynamic smem layout (byte offsets, all 16B-aligned):
    //   [0      : 12288)  xstage[2][384] float4
    //   [12288  : 86016)  wsm[24][384]   u64
    //   [86016  : 88064)  h_s[4][128]    float
    //   [88064  : 90112)  rbuf[128]      float4
    //   [90112  : 92160)  zbuf[128]      float4
    extern __shared__ char dsm[];
    float4* xstage = reinterpret_cast<float4*>(dsm);
    u64*    wsm    = reinterpret_cast<u64*>(dsm + 12288);
    float*  h_s    = reinterpret_cast<float*>(dsm + 86016);
    float4* rbuf   = reinterpret_cast<float4*>(dsm + 88064);
    float4* zbuf   = reinterpret_cast<float4*>(dsm + 90112);

    const int g  = threadIdx.x;
    const int rb = blockIdx.x * 4;

    const u64* wrow = reinterpret_cast<const u64*>(Whh + (size_t)g * H_);
    // k-pairs 0..23 -> smem (k-major: wsm[p*384 + g])
#pragma unroll
    for (int p = 0; p < 24; ++p) wsm[p * G_ + g] = wrow[p];
    // k-pairs 24..63 -> registers
    u64 wpr[40];
#pragma unroll
    for (int i = 0; i < 40; ++i) wpr[i] = wrow[24 + i];
    const float bh = bhh[g];

    for (int idx = g; idx < 4 * H_; idx += 384) h_s[idx] = 0.f;
    __syncthreads();

    const int sec = g >> 7;
    const int j   = g & 127;

    const float* xp = g_xg + (size_t)blockIdx.x * S_ * (G_ * 4) + g * 4;
    float* hall = g_h1 + ((size_t)rb * S_) * H_ + j;

    const uint32_t xs0 = smem_u32(&xstage[g]);
    const uint32_t xs1 = smem_u32(&xstage[G_ + g]);

    cp_async16(xs0, xp, 1);
    cp_commit();
    xp += G_ * 4;

    float hp0 = 0.f, hp1 = 0.f, hp2 = 0.f, hp3 = 0.f;

    const ulonglong2* hr0 = reinterpret_cast<const ulonglong2*>(h_s);
    const ulonglong2* hr1 = hr0 + 32;
    const ulonglong2* hr2 = hr0 + 64;
    const ulonglong2* hr3 = hr0 + 96;

    for (int t = 0; t < S_; ++t) {
        cp_async16((t & 1) ? xs0 : xs1, xp, t + 1 < S_);
        cp_commit();
        xp += G_ * 4;

        // -------- pipelined dot: h(t-1) . w for 4 rows --------
        u64 a0 = 0ull, a1 = 0ull, a2 = 0ull, a3 = 0ull;
        ulonglong2 hb0[2], hb1[2], hb2[2], hb3[2];
        u64 wb0[2], wb1[2];
        hb0[0] = hr0[0]; hb1[0] = hr1[0]; hb2[0] = hr2[0]; hb3[0] = hr3[0];
        wb0[0] = wsm[0 * G_ + g];
        wb1[0] = wsm[1 * G_ + g];
#pragma unroll
        for (int kk = 0; kk < 32; ++kk) {
            const int c = kk & 1, n = c ^ 1;
            if (kk < 31) {
                hb0[n] = hr0[kk + 1];
                hb1[n] = hr1[kk + 1];
                hb2[n] = hr2[kk + 1];
                hb3[n] = hr3[kk + 1];
            }
            if (kk < 11) {
                wb0[n] = wsm[(2 * kk + 2) * G_ + g];
                wb1[n] = wsm[(2 * kk + 3) * G_ + g];
            }
            u64 w0 = (kk < 12) ? wb0[c] : wpr[2 * (kk - 12)];
            u64 w1 = (kk < 12) ? wb1[c] : wpr[2 * (kk - 12) + 1];
            fma2(a0, hb0[c].x, w0);
            fma2(a1, hb1[c].x, w0);
            fma2(a2, hb2[c].x, w0);
            fma2(a3, hb3[c].x, w0);
            fma2(a0, hb0[c].y, w1);
            fma2(a1, hb1[c].y, w1);
            fma2(a2, hb2[c].y, w1);
            fma2(a3, hb3[c].y, w1);
        }
        float g0, g1, g2, g3, tlo, thi;
        upk2(a0, tlo, thi); g0 = tlo + thi + bh;
        upk2(a1, tlo, thi); g1 = tlo + thi + bh;
        upk2(a2, tlo, thi); g2 = tlo + thi + bh;
        upk2(a3, tlo, thi); g3 = tlo + thi + bh;

        cp_wait1();
        float4 xv = (t & 1) ? xstage[G_ + g] : xstage[g];

        if (sec == 0) {
            rbuf[j] = make_float4(sig_ap(xv.x + g0), sig_ap(xv.y + g1),
                                  sig_ap(xv.z + g2), sig_ap(xv.w + g3));
        } else if (sec == 1) {
            zbuf[j] = make_float4(sig_ap(xv.x + g0), sig_ap(xv.y + g1),
                                  sig_ap(xv.z + g2), sig_ap(xv.w + g3));
        }
        __syncthreads();
        if (sec == 2) {
            float4 rr = rbuf[j];
            float4 zz = zbuf[j];
            float n0 = tanh_ap(fmaf(rr.x, g0, xv.x));
            float n1 = tanh_ap(fmaf(rr.y, g1, xv.y));
            float n2 = tanh_ap(fmaf(rr.z, g2, xv.z));
            float n3 = tanh_ap(fmaf(rr.w, g3, xv.w));
            hp0 = fmaf(zz.x, hp0 - n0, n0);
            hp1 = fmaf(zz.y, hp1 - n1, n1);
            hp2 = fmaf(zz.z, hp2 - n2, n2);
            hp3 = fmaf(zz.w, hp3 - n3, n3);
            h_s[0 * H_ + j] = hp0;
            h_s[1 * H_ + j] = hp1;
            h_s[2 * H_ + j] = hp2;
            h_s[3 * H_ + j] = hp3;
            if (WRITE_ALL) {
                hall[0]                        = hp0;
                hall[(size_t)S_ * H_]          = hp1;
                hall[2 * (size_t)S_ * H_]      = hp2;
                hall[3 * (size_t)S_ * H_]      = hp3;
            }
        }
        __syncthreads();
        if (WRITE_ALL) hall += H_;
    }

    // -------- fused FC head (layer 2 only): out = h_final @ fc_w^T + fc_b ----
    if (!WRITE_ALL) {
        if (g < 4 * C_) {
            const int b = g / C_;
            const int c = g - b * C_;
            float acc = fb[c];
#pragma unroll
            for (int jj = 0; jj < H_; ++jj)
                acc += h_s[b * H_ + jj] * fw[c * H_ + jj];
            out[(rb + b) * C_ + c] = acc;
        }
    }
}

extern "C" void kernel_launch(void* const* d_in, const int* in_sizes, int n_in,
                              void* d_out, int out_size)
{
    (void)in_sizes; (void)n_in; (void)out_size;
    const float* x      = (const float*)d_in[0];
    const float* W_ih0  = (const float*)d_in[1];
    const float* W_hh0  = (const float*)d_in[2];
    const float* b_ih0  = (const float*)d_in[3];
    const float* b_hh0  = (const float*)d_in[4];
    const float* W_ih1  = (const float*)d_in[5];
    const float* W_hh1  = (const float*)d_in[6];
    const float* b_ih1  = (const float*)d_in[7];
    const float* b_hh1  = (const float*)d_in[8];
    const float* fc_w   = (const float*)d_in[9];
    const float* fc_b   = (const float*)d_in[10];
    float* out = (float*)d_out;

    const int ntiles = (B_ / 4) * (S_ / 16);   // 8192
    const int smem64  = 64  * 4 * (G_ + 64);   // 114688 B
    const int smem128 = 128 * 4 * (G_ + 64);   // 229376 B
    const int smemrec = 92160;                 // xstage + wsm + h_s + rbuf + zbuf

    cudaFuncSetAttribute(gemm_xg_kernel<64, false>,
                         cudaFuncAttributeMaxDynamicSharedMemorySize, smem64);
    cudaFuncSetAttribute(gemm_xg_kernel<128, true>,
                         cudaFuncAttributeMaxDynamicSharedMemorySize, smem128);
    cudaFuncSetAttribute(gru_rec_kernel<true>,
                         cudaFuncAttributeMaxDynamicSharedMemorySize, smemrec);
    cudaFuncSetAttribute(gru_rec_kernel<false>,
                         cudaFuncAttributeMaxDynamicSharedMemorySize, smemrec);

    // Layer 0
    gemm_xg_kernel<64, false><<<148, 256, smem64>>>(x, W_ih0, b_ih0, ntiles);
    gru_rec_kernel<true><<<128, 384, smemrec>>>(W_hh0, b_hh0, fc_w, fc_b, out);
    // Layer 1
    gemm_xg_kernel<128, true><<<148, 256, smem128>>>(nullptr, W_ih1, b_ih1, ntiles);
    gru_rec_kernel<false><<<128, 384, smemrec>>>(W_hh1, b_hh1, fc_w, fc_b, out);
}

// round 17
// speedup vs baseline: 1.1190x; 1.1190x over previous
#include <cuda_runtime.h>
#include <cstdint>
#include <cstddef>

// Problem dims
#define B_  512
#define S_  1024
#define I_  64
#define H_  128
#define G_  384   // 3*H
#define C_  10

// Scratch (device globals: allocation APIs are forbidden)
// g_xg layout: INTERLEAVED [b/4][s][g][4] so one rec-CTA's 4 batch rows for a
// given (s, gate) are 16 contiguous bytes -> single cp.async.16B per step.
__device__ float g_xg[(size_t)B_ * S_ * G_];
__device__ float g_h1[(size_t)B_ * S_ * H_];    // layer0 hidden outputs [b][s][h]

typedef unsigned long long u64;

__device__ __forceinline__ u64 pk2(float lo, float hi) {
    u64 r; asm("mov.b64 %0, {%1, %2};" : "=l"(r) : "f"(lo), "f"(hi)); return r;
}
__device__ __forceinline__ void upk2(u64 v, float& lo, float& hi) {
    asm("mov.b64 {%0, %1}, %2;" : "=f"(lo), "=f"(hi) : "l"(v));
}
__device__ __forceinline__ void fma2(u64& d, u64 a, u64 b) {
    asm("fma.rn.f32x2 %0, %1, %2, %0;" : "+l"(d) : "l"(a), "l"(b));
}

// MUFU.TANH — single-op tanh (sm_75+)
__device__ __forceinline__ float tanh_ap(float x) {
    float y; asm("tanh.approx.f32 %0, %1;" : "=f"(y) : "f"(x)); return y;
}
__device__ __forceinline__ float sig_ap(float x) {
    return fmaf(tanh_ap(0.5f * x), 0.5f, 0.5f);
}

__device__ __forceinline__ uint32_t smem_u32(const void* p) {
    uint32_t a;
    asm("{ .reg .u64 t; cvta.to.shared.u64 t, %1; cvt.u32.u64 %0, t; }"
        : "=r"(a) : "l"(p));
    return a;
}
// Predicated 16-byte cp.async (.cg: bypass L1, xg is read exactly once)
__device__ __forceinline__ void cp_async16(uint32_t dst, const float* src, int pred) {
    asm volatile(
        "{\n\t.reg .pred p;\n\tsetp.ne.u32 p, %2, 0;\n\t"
        "@p cp.async.cg.shared.global [%0], [%1], 16;\n\t}"
        :: "r"(dst), "l"(src), "r"(pred) : "memory");
}
__device__ __forceinline__ void cp_commit() {
    asm volatile("cp.async.commit_group;" ::: "memory");
}
__device__ __forceinline__ void cp_wait1() {
    asm volatile("cp.async.wait_group 1;" ::: "memory");
}

// ============================================================================
// Phase 1/3: xg = A @ W^T + bias, interleaved output (R9 GEMM; unroll 4)
//   element (b, s, g) -> g_xg[(((b>>2)*S + s)*G + g)*4 + (b&3)]
// Tile = 4 batches x 16 timesteps (64 rows). Warp rg computes rows {rg + 8r}:
// each thread holds all 4 b-lanes of (s,g) quads -> coalesced STG.128.
// ============================================================================
template<int K, bool A_IS_H1>
__global__ __launch_bounds__(256) void gemm_xg_kernel(
    const float* __restrict__ Ain, const float* __restrict__ W,
    const float* __restrict__ bias, int ntiles)
{
    extern __shared__ float smem[];
    float* Ws = smem;              // [K][384], k-major
    float* As = smem + K * G_;     // [64][K]
    const float* A = A_IS_H1 ? g_h1 : Ain;

    const int tid = threadIdx.x;
    constexpr int KQ = K / 4;
    constexpr int PF = (64 * KQ) / 256;

    for (int idx = tid; idx < G_ * KQ; idx += 256) {
        int kq = idx / G_;
        int g  = idx - kq * G_;
        float4 w4 = *reinterpret_cast<const float4*>(W + (size_t)g * K + 4 * kq);
        Ws[(4 * kq + 0) * G_ + g] = w4.x;
        Ws[(4 * kq + 1) * G_ + g] = w4.y;
        Ws[(4 * kq + 2) * G_ + g] = w4.z;
        Ws[(4 * kq + 3) * G_ + g] = w4.w;
    }

    const int cg = tid & 31;
    const int rg = tid >> 5;

    float4 bv[3];
#pragma unroll
    for (int gg = 0; gg < 3; ++gg)
        bv[gg] = *reinterpret_cast<const float4*>(bias + gg * H_ + 4 * cg);

    auto tile_src = [&](int tl, int i) -> const float4* {
        int idx = tid + 256 * i;
        int r   = idx / KQ;
        int c   = idx - r * KQ;
        int bq  = tl >> 6;
        int s0  = (tl & 63) << 4;
        size_t row = (size_t)(4 * bq + (r >> 4)) * S_ + s0 + (r & 15);
        return reinterpret_cast<const float4*>(A + row * K) + c;
    };

    int tile = blockIdx.x;
    float4 pf[PF];
    if (tile < ntiles) {
#pragma unroll
        for (int i = 0; i < PF; ++i) pf[i] = *tile_src(tile, i);
    }
    __syncthreads();

    for (; tile < ntiles; tile += gridDim.x) {
#pragma unroll
        for (int i = 0; i < PF; ++i)
            reinterpret_cast<float4*>(As)[tid + 256 * i] = pf[i];
        __syncthreads();

        int ntile = tile + gridDim.x;
        if (ntile < ntiles) {
#pragma unroll
            for (int i = 0; i < PF; ++i) pf[i] = *tile_src(ntile, i);
        }

        u64 acc[8][3][2];
#pragma unroll
        for (int r = 0; r < 8; ++r)
#pragma unroll
            for (int gg = 0; gg < 3; ++gg) {
                acc[r][gg][0] = 0ull;
                acc[r][gg][1] = 0ull;
            }

#pragma unroll 4
        for (int k4 = 0; k4 < K; k4 += 4) {
            float4 af[8];
#pragma unroll
            for (int r = 0; r < 8; ++r)
                af[r] = *reinterpret_cast<const float4*>(&As[(rg + 8 * r) * K + k4]);
#pragma unroll
            for (int kk = 0; kk < 4; ++kk) {
                ulonglong2 wp[3];
#pragma unroll
                for (int gg = 0; gg < 3; ++gg)
                    wp[gg] = *reinterpret_cast<const ulonglong2*>(
                        &Ws[(size_t)(k4 + kk) * G_ + gg * H_ + 4 * cg]);
#pragma unroll
                for (int r = 0; r < 8; ++r) {
                    float a = (kk == 0) ? af[r].x : (kk == 1) ? af[r].y
                            : (kk == 2) ? af[r].z : af[r].w;
                    u64 ad = pk2(a, a);
#pragma unroll
                    for (int gg = 0; gg < 3; ++gg) {
                        fma2(acc[r][gg][0], ad, wp[gg].x);
                        fma2(acc[r][gg][1], ad, wp[gg].y);
                    }
                }
            }
        }

        // Interleaved store: row r = rg + 8r' -> b-lane = r'>>1, si = r'&1
        {
            const int bq = tile >> 6;
            const int s0 = (tile & 63) << 4;
#pragma unroll
            for (int si = 0; si < 2; ++si) {
                const int s = s0 + rg + 8 * si;
                float* Crow = g_xg + ((size_t)bq * S_ + s) * (G_ * 4);
#pragma unroll
                for (int gg = 0; gg < 3; ++gg) {
                    float q0[4], q1[4], q2[4], q3[4];
#pragma unroll
                    for (int b = 0; b < 4; ++b) {
                        upk2(acc[2 * b + si][gg][0], q0[b], q1[b]);
                        upk2(acc[2 * b + si][gg][1], q2[b], q3[b]);
                    }
                    float* p = Crow + (gg * H_ + 4 * cg) * 4;
                    *reinterpret_cast<float4*>(p)      = make_float4(
                        q0[0] + bv[gg].x, q0[1] + bv[gg].x, q0[2] + bv[gg].x, q0[3] + bv[gg].x);
                    *reinterpret_cast<float4*>(p + 4)  = make_float4(
                        q1[0] + bv[gg].y, q1[1] + bv[gg].y, q1[2] + bv[gg].y, q1[3] + bv[gg].y);
                    *reinterpret_cast<float4*>(p + 8)  = make_float4(
                        q2[0] + bv[gg].z, q2[1] + bv[gg].z, q2[2] + bv[gg].z, q2[3] + bv[gg].z);
                    *reinterpret_cast<float4*>(p + 12) = make_float4(
                        q3[0] + bv[gg].w, q3[1] + bv[gg].w, q3[2] + bv[gg].w, q3[3] + bv[gg].w);
                }
            }
        }
        __syncthreads();
    }
}

// ============================================================================
// Phase 2/4: recurrent scan — R9 structure byte-for-byte, plus a fused FC
// head in rec<false> (reads final h from h_s; no g_h2last round-trip).
// ============================================================================
template<bool WRITE_ALL>
__global__ __launch_bounds__(384, 1) void gru_rec_kernel(
    const float* __restrict__ Whh, const float* __restrict__ bhh,
    const float* __restrict__ fw, const float* __restrict__ fb,
    float* __restrict__ out)
{
    __shared__ float h_s[4][H_];
    __shared__ float4 rbuf[H_];
    __shared__ float4 zbuf[H_];
    __shared__ float4 xstage[2][G_];

    const int g  = threadIdx.x;
    const int rb = blockIdx.x * 4;

    u64 wp[64];
    const u64* wrow = reinterpret_cast<const u64*>(Whh + (size_t)g * H_);
#pragma unroll
    for (int kk = 0; kk < 64; ++kk) wp[kk] = wrow[kk];
    const float bh = bhh[g];

    for (int idx = g; idx < 4 * H_; idx += 384)
        (&h_s[0][0])[idx] = 0.f;
    __syncthreads();

    const int sec = g >> 7;
    const int j   = g & 127;

    const float* xp = g_xg + (size_t)blockIdx.x * S_ * (G_ * 4) + g * 4;
    float* hall = g_h1 + ((size_t)rb * S_) * H_ + j;

    const uint32_t xs0 = smem_u32(&xstage[0][g]);
    const uint32_t xs1 = smem_u32(&xstage[1][g]);

    cp_async16(xs0, xp, 1);
    cp_commit();
    xp += G_ * 4;

    float hp0 = 0.f, hp1 = 0.f, hp2 = 0.f, hp3 = 0.f;

    const ulonglong2* hr0 = reinterpret_cast<const ulonglong2*>(h_s[0]);
    const ulonglong2* hr1 = reinterpret_cast<const ulonglong2*>(h_s[1]);
    const ulonglong2* hr2 = reinterpret_cast<const ulonglong2*>(h_s[2]);
    const ulonglong2* hr3 = reinterpret_cast<const ulonglong2*>(h_s[3]);

    for (int t = 0; t < S_; ++t) {
        cp_async16((t & 1) ? xs0 : xs1, xp, t + 1 < S_);
        cp_commit();
        xp += G_ * 4;

        u64 a0 = 0ull, a1 = 0ull, a2 = 0ull, a3 = 0ull;
#pragma unroll
        for (int kk = 0; kk < 32; ++kk) {
            ulonglong2 h0 = hr0[kk];
            ulonglong2 h1 = hr1[kk];
            ulonglong2 h2 = hr2[kk];
            ulonglong2 h3 = hr3[kk];
            u64 w0 = wp[2 * kk];
            u64 w1 = wp[2 * kk + 1];
            fma2(a0, h0.x, w0);
            fma2(a1, h1.x, w0);
            fma2(a2, h2.x, w0);
            fma2(a3, h3.x, w0);
            fma2(a0, h0.y, w1);
            fma2(a1, h1.y, w1);
            fma2(a2, h2.y, w1);
            fma2(a3, h3.y, w1);
        }
        float g0, g1, g2, g3, tlo, thi;
        upk2(a0, tlo, thi); g0 = tlo + thi + bh;
        upk2(a1, tlo, thi); g1 = tlo + thi + bh;
        upk2(a2, tlo, thi); g2 = tlo + thi + bh;
        upk2(a3, tlo, thi); g3 = tlo + thi + bh;

        cp_wait1();
        float4 xv = (t & 1) ? xstage[1][g] : xstage[0][g];

        if (sec == 0) {
            rbuf[j] = make_float4(sig_ap(xv.x + g0), sig_ap(xv.y + g1),
                                  sig_ap(xv.z + g2), sig_ap(xv.w + g3));
        } else if (sec == 1) {
            zbuf[j] = make_float4(sig_ap(xv.x + g0), sig_ap(xv.y + g1),
                                  sig_ap(xv.z + g2), sig_ap(xv.w + g3));
        }
        __syncthreads();
        if (sec == 2) {
            float4 rr = rbuf[j];
            float4 zz = zbuf[j];
            float n0 = tanh_ap(fmaf(rr.x, g0, xv.x));
            float n1 = tanh_ap(fmaf(rr.y, g1, xv.y));
            float n2 = tanh_ap(fmaf(rr.z, g2, xv.z));
            float n3 = tanh_ap(fmaf(rr.w, g3, xv.w));
            hp0 = fmaf(zz.x, hp0 - n0, n0);
            hp1 = fmaf(zz.y, hp1 - n1, n1);
            hp2 = fmaf(zz.z, hp2 - n2, n2);
            hp3 = fmaf(zz.w, hp3 - n3, n3);
            h_s[0][j] = hp0;
            h_s[1][j] = hp1;
            h_s[2][j] = hp2;
            h_s[3][j] = hp3;
            if (WRITE_ALL) {
                hall[0]                        = hp0;
                hall[(size_t)S_ * H_]          = hp1;
                hall[2 * (size_t)S_ * H_]      = hp2;
                hall[3 * (size_t)S_ * H_]      = hp3;
            }
        }
        __syncthreads();
        if (WRITE_ALL) hall += H_;
    }

    // Fused FC head (layer 2 only): out[rb+b][c] = h_s[b] . fc_w[c] + fc_b[c]
    if (!WRITE_ALL) {
        if (g < 4 * C_) {
            const int b = g / C_;
            const int c = g - b * C_;
            float acc = fb[c];
#pragma unroll
            for (int jj = 0; jj < H_; ++jj)
                acc += h_s[b][jj] * fw[c * H_ + jj];
            out[(rb + b) * C_ + c] = acc;
        }
    }
}

extern "C" void kernel_launch(void* const* d_in, const int* in_sizes, int n_in,
                              void* d_out, int out_size)
{
    (void)in_sizes; (void)n_in; (void)out_size;
    const float* x      = (const float*)d_in[0];
    const float* W_ih0  = (const float*)d_in[1];
    const float* W_hh0  = (const float*)d_in[2];
    const float* b_ih0  = (const float*)d_in[3];
    const float* b_hh0  = (const float*)d_in[4];
    const float* W_ih1  = (const float*)d_in[5];
    const float* W_hh1  = (const float*)d_in[6];
    const float* b_ih1  = (const float*)d_in[7];
    const float* b_hh1  = (const float*)d_in[8];
    const float* fc_w   = (const float*)d_in[9];
    const float* fc_b   = (const float*)d_in[10];
    float* out = (float*)d_out;

    const int ntiles = (B_ / 4) * (S_ / 16);   // 8192
    const int smem64  = 64  * 4 * (G_ + 64);   // 114688 B
    const int smem128 = 128 * 4 * (G_ + 64);   // 229376 B

    cudaFuncSetAttribute(gemm_xg_kernel<64, false>,
                         cudaFuncAttributeMaxDynamicSharedMemorySize, smem64);
    cudaFuncSetAttribute(gemm_xg_kernel<128, true>,
                         cudaFuncAttributeMaxDynamicSharedMemorySize, smem128);

    // Layer 0
    gemm_xg_kernel<64, false><<<148, 256, smem64>>>(x, W_ih0, b_ih0, ntiles);
    gru_rec_kernel<true><<<128, 384>>>(W_hh0, b_hh0, fc_w, fc_b, out);
    // Layer 1
    gemm_xg_kernel<128, true><<<148, 256, smem128>>>(nullptr, W_ih1, b_ih1, ntiles);
    gru_rec_kernel<false><<<128, 384>>>(W_hh1, b_hh1, fc_w, fc_b, out);
}